// round 14
// baseline (speedup 1.0000x reference)
#include <cuda_runtime.h>
#include <cuda_fp16.h>
#include <math.h>
#include <stdint.h>

#define BB 8
#define LL 1024
#define DIN 256
#define HH 512
#define NHEAD 8
#define MROWS (BB*LL)   // 8192

// ---------------- scratch (device globals; no allocations) ----------------
__device__ float  g_x    [MROWS*HH];
__device__ __half g_xh   [MROWS*HH];
__device__ float  g_loc  [MROWS*HH];
__device__ __half g_loch [MROWS*HH];
__device__ float  g_qkv  [MROWS*3*HH];
__device__ __half g_atth [MROWS*HH];
__device__ float  g_att  [MROWS*HH];
__device__ float  g_tmp  [MROWS*HH];
__device__ __half g_tmp1h[MROWS*2*HH];
__device__ float  g_comb [MROWS*HH];
__device__ __half g_combh[MROWS*HH];
__device__ __half g_sih  [MROWS*544];
__device__ float  g_h256 [MROWS*256];
__device__ float  g_pmean[16*BB*HH];
__device__ float  g_gpart[BB*HH];
__device__ float  g_bsa  [512];
__device__ __half g_steh [MROWS*DIN];
__device__ __half g_wt   [3948544];

// transposed-weight offsets (halves)
#define WT_P    0
#define WT_QKV0 131072
#define WT_QKV1 917504
#define WT_O0   1703936
#define WT_O1   1966080
#define WT_C    2228224
#define WT_1    2490368
#define WT_2    3014656
#define WT_T1   3538944
#define WT_SA   3670016

// ---------------- helpers ---------------------------------------------------
__device__ __forceinline__ uint32_t s2u(const void* p) {
    uint32_t a;
    asm("{ .reg .u64 t; cvta.to.shared.u64 t, %1; cvt.u32.u64 %0, t; }" : "=r"(a) : "l"(p));
    return a;
}
__device__ __forceinline__ void cpa16(uint32_t sdst, const void* gsrc) {
    asm volatile("cp.async.cg.shared.global [%0], [%1], 16;" :: "r"(sdst), "l"(gsrc) : "memory");
}
#define CP_COMMIT() asm volatile("cp.async.commit_group;" ::: "memory")
#define CP_WAIT3()  asm volatile("cp.async.wait_group 3;" ::: "memory")

__device__ __forceinline__ void ldsm4(uint32_t& r0, uint32_t& r1, uint32_t& r2, uint32_t& r3,
                                      uint32_t addr) {
    asm volatile("ldmatrix.sync.aligned.m8n8.x4.shared.b16 {%0,%1,%2,%3}, [%4];"
                 : "=r"(r0), "=r"(r1), "=r"(r2), "=r"(r3) : "r"(addr));
}

__device__ __forceinline__ void mma_f16(
    float& d0, float& d1, float& d2, float& d3,
    uint32_t a0, uint32_t a1, uint32_t a2, uint32_t a3,
    uint32_t b0, uint32_t b1)
{
    asm volatile(
        "mma.sync.aligned.m16n8k16.row.col.f32.f16.f16.f32 "
        "{%0,%1,%2,%3}, {%4,%5,%6,%7}, {%8,%9}, {%0,%1,%2,%3};"
        : "+f"(d0), "+f"(d1), "+f"(d2), "+f"(d3)
        : "r"(a0), "r"(a1), "r"(a2), "r"(a3), "r"(b0), "r"(b1));
}

// ---------------- fp16 cp.async GEMM with ldmatrix ---------------------------
// Block 128x128, 256 thr (8 warps 4x2, warp 32x64), 5-stage cp.async
// (wait_group 3, always-commit), 2 CTAs/SM.  M%128==0, N%128==0, K%32==0, nk>=4.
#define RS 40
#define ST_MAT_H (128*RS)
#define ST_BYTES (2*ST_MAT_H*2)       // 20480 B per stage
#define NSTG 5
#define SMEM_H   (NSTG*ST_BYTES)      // 102400 B

template<int ACT, bool BBIAS, bool RES, bool WF, bool WH>
__global__ __launch_bounds__(256, 2) void gemm_h(
    const __half* __restrict__ A, int lda,
    const __half* __restrict__ Wt,
    const float* __restrict__ bias,
    const float* __restrict__ gb,
    const float* __restrict__ res,
    float* __restrict__ Cf, __half* __restrict__ Ch,
    int N, int K)
{
    extern __shared__ __half smh[];
    const uint32_t sbase = s2u(smh);

    const int tid  = threadIdx.x;
    const int warp = tid >> 5;
    const int lane = tid & 31;
    const int wm = warp >> 1;
    const int wn = warp & 1;
    const int qr = lane >> 2;
    const int qc = lane & 3;

    const int lrow = (lane & 7) + 8*((lane >> 3) & 1);
    const int lk   = 8*(lane >> 4);

    const int m0 = blockIdx.y * 128;
    const int n0 = blockIdx.x * 128;
    const int nk = K >> 5;

#define STAGE_LOAD(kt) do {                                                     \
        const uint32_t sA = sbase + ((kt) % NSTG) * ST_BYTES;                   \
        const uint32_t sB = sA + ST_MAT_H*2;                                    \
        _Pragma("unroll")                                                       \
        for (int it = 0; it < 2; it++) {                                        \
            const int id  = tid + 256*it;                                       \
            const int row = id >> 2;                                            \
            const int c8  = (id & 3) * 8;                                       \
            cpa16(sA + (row*RS + c8)*2,                                         \
                  A  + (size_t)(m0 + row)*lda + (kt)*32 + c8);                  \
            cpa16(sB + (row*RS + c8)*2,                                         \
                  Wt + (size_t)(n0 + row)*K   + (kt)*32 + c8);                  \
        }                                                                       \
        CP_COMMIT();                                                            \
    } while (0)

    float acc[2][8][4];
#pragma unroll
    for (int i = 0; i < 2; i++)
#pragma unroll
        for (int j = 0; j < 8; j++)
#pragma unroll
            for (int c = 0; c < 4; c++) acc[i][j][c] = 0.f;

    STAGE_LOAD(0);
    STAGE_LOAD(1);
    STAGE_LOAD(2);
    STAGE_LOAD(3);

    for (int kt = 0; kt < nk; kt++) {
        CP_WAIT3();
        __syncthreads();
        if (kt + 4 < nk) STAGE_LOAD(kt + 4); else CP_COMMIT();

        const uint32_t sA = sbase + (kt % NSTG) * ST_BYTES;
        const uint32_t sB = sA + ST_MAT_H*2;
#pragma unroll
        for (int kk = 0; kk < 32; kk += 16) {
            uint32_t a[2][4], b[4][4];
#pragma unroll
            for (int mf = 0; mf < 2; mf++) {
                const uint32_t ad = sA + ((wm*32 + mf*16 + lrow)*RS + kk + lk)*2;
                ldsm4(a[mf][0], a[mf][1], a[mf][2], a[mf][3], ad);
            }
#pragma unroll
            for (int ng = 0; ng < 4; ng++) {
                const uint32_t bd = sB + ((wn*64 + ng*16 + lrow)*RS + kk + lk)*2;
                ldsm4(b[ng][0], b[ng][1], b[ng][2], b[ng][3], bd);
            }
#pragma unroll
            for (int mf = 0; mf < 2; mf++)
#pragma unroll
                for (int ng = 0; ng < 4; ng++) {
                    mma_f16(acc[mf][2*ng][0], acc[mf][2*ng][1],
                            acc[mf][2*ng][2], acc[mf][2*ng][3],
                            a[mf][0], a[mf][1], a[mf][2], a[mf][3],
                            b[ng][0], b[ng][2]);
                    mma_f16(acc[mf][2*ng+1][0], acc[mf][2*ng+1][1],
                            acc[mf][2*ng+1][2], acc[mf][2*ng+1][3],
                            a[mf][0], a[mf][1], a[mf][2], a[mf][3],
                            b[ng][1], b[ng][3]);
                }
        }
    }

    // epilogue
    const int batch = m0 >> 10;
#pragma unroll
    for (int mf = 0; mf < 2; mf++) {
#pragma unroll
        for (int nf = 0; nf < 8; nf++) {
            const int n = n0 + wn*64 + nf*8 + qc*2;
            float bx = 0.f, by = 0.f;
            if (bias) { bx = bias[n]; by = bias[n+1]; }
            if (BBIAS) { bx += gb[batch*N + n]; by += gb[batch*N + n + 1]; }
#pragma unroll
            for (int half = 0; half < 2; half++) {
                const int m = m0 + wm*32 + mf*16 + qr + half*8;
                float v0 = acc[mf][nf][half*2+0] + bx;
                float v1 = acc[mf][nf][half*2+1] + by;
                if (RES) {
                    const float2 r2 = *(const float2*)&res[(size_t)m*N + n];
                    v0 += r2.x; v1 += r2.y;
                }
                if (ACT == 1) { v0 = fmaxf(v0, 0.f); v1 = fmaxf(v1, 0.f); }
                else if (ACT == 2) {
                    v0 = 0.5f*v0*(1.f + erff(v0*0.70710678118654752f));
                    v1 = 0.5f*v1*(1.f + erff(v1*0.70710678118654752f));
                }
                if (WF) *(float2*)&Cf[(size_t)m*N + n] = make_float2(v0, v1);
                if (WH) *(__half2*)&Ch[(size_t)m*N + n] =
                            __halves2half2(__float2half_rn(v0), __float2half_rn(v1));
            }
        }
    }
#undef STAGE_LOAD
}

// ---------------- merged weight transpose (f32 -> fp16 [N][K]) --------------
#define NJOBS 11
struct TransJobs {
    const float* src[NJOBS];
    long long    dstoff[NJOBS];
    int K[NJOBS], N[NJOBS];
    int start[NJOBS+1];
};

__global__ __launch_bounds__(256) void transpose_all_kernel(TransJobs jobs, __half* __restrict__ wt)
{
    __shared__ float t[32][33];
    const int bid = blockIdx.x;
    int j = 0;
#pragma unroll
    for (int i = 0; i < NJOBS; i++) if (bid >= jobs.start[i+1]) j = i+1;
    const int lt = bid - jobs.start[j];
    const int K = jobs.K[j], N = jobs.N[j];
    const int tilesx = N >> 5;
    const int n0 = (lt % tilesx) * 32;
    const int k0 = (lt / tilesx) * 32;
    const float* in = jobs.src[j];
    __half* outp = wt + jobs.dstoff[j];

    const int x = threadIdx.x & 31, y = threadIdx.x >> 5;
#pragma unroll
    for (int i = 0; i < 4; i++)
        t[y + 8*i][x] = in[(size_t)(k0 + y + 8*i) * N + n0 + x];
    __syncthreads();
#pragma unroll
    for (int i = 0; i < 4; i++)
        outp[(size_t)(n0 + y + 8*i) * K + k0 + x] = __float2half_rn(t[x][y + 8*i]);
}

// ---------------- f32 -> fp16 convert (state) -------------------------------
__global__ void tohalf_kernel(const float* __restrict__ in, __half* __restrict__ o, int n2)
{
    const int i = blockIdx.x*256 + threadIdx.x;
    if (i < n2) {
        const float2 v = ((const float2*)in)[i];
        ((__half2*)o)[i] = __halves2half2(__float2half_rn(v.x), __float2half_rn(v.y));
    }
}

// ---------------- windowed attention (NATTEN, window 31) -------------------
// [r][d] DYNAMIC smem, stride 68 floats (272 B): float4 loads legal AND
// conflict-free.  51,136 B > 48KB static limit -> dynamic + attribute opt-in.
#define NAT_RS 68
#define SMEM_NAT (2*94*NAT_RS*4)      // 51136 B

__global__ __launch_bounds__(64) void natten_kernel(
    const float* __restrict__ qkv, __half* __restrict__ out)
{
    extern __shared__ float nsm[];
    float (*ks)[NAT_RS] = (float(*)[NAT_RS])nsm;
    float (*vs)[NAT_RS] = (float(*)[NAT_RS])(nsm + 94*NAT_RS);

    const int qt = blockIdx.x;
    const int h  = blockIdx.y;
    const int b  = blockIdx.z;
    const int q0 = qt * 64;
    const int base = q0 - 15;

    const int tid = threadIdx.x;
    for (int idx = tid; idx < 94*16; idx += 64) {
        const int r  = idx >> 4;
        const int d4 = (idx & 15) * 4;
        const int pos = base + r;
        float4 kk4 = make_float4(0.f,0.f,0.f,0.f);
        float4 vv4 = make_float4(0.f,0.f,0.f,0.f);
        if (pos >= 0 && pos < LL) {
            const size_t off = ((size_t)(b*LL + pos))*1536 + h*64 + d4;
            kk4 = *(const float4*)&qkv[off + 512];
            vv4 = *(const float4*)&qkv[off + 1024];
        }
        *(float4*)&ks[r][d4] = kk4;
        *(float4*)&vs[r][d4] = vv4;
    }
    __syncthreads();

    const int l = q0 + tid;
    const float* qp = &qkv[((size_t)(b*LL + l))*1536 + h*64];

    float s[31];
#pragma unroll
    for (int j = 0; j < 31; j++) s[j] = 0.f;

#pragma unroll
    for (int c = 0; c < 4; c++) {
        float q[16];
#pragma unroll
        for (int d4 = 0; d4 < 16; d4 += 4)
            *(float4*)&q[d4] = *(const float4*)&qp[c*16 + d4];
#pragma unroll
        for (int j = 0; j < 31; j++) {
            float kv[16];
#pragma unroll
            for (int d4 = 0; d4 < 16; d4 += 4)
                *(float4*)&kv[d4] = *(const float4*)&ks[tid + j][c*16 + d4];
            float dot = 0.f;
#pragma unroll
            for (int d = 0; d < 16; d++)
                dot = fmaf(q[d], kv[d], dot);
            s[j] += dot;
        }
    }

    float mx = -1e30f;
#pragma unroll
    for (int j = 0; j < 31; j++) {
        const int pos = l - 15 + j;
        if (pos < 0 || pos >= LL) s[j] = -1e30f;
        else                      s[j] *= 0.125f;
        mx = fmaxf(mx, s[j]);
    }
    float sum = 0.f;
#pragma unroll
    for (int j = 0; j < 31; j++) { s[j] = expf(s[j] - mx); sum += s[j]; }
    const float inv = 1.f / sum;

    __half* op = &out[((size_t)(b*LL + l))*512 + h*64];
#pragma unroll
    for (int c = 0; c < 4; c++) {
        float o[16];
#pragma unroll
        for (int d = 0; d < 16; d++) o[d] = 0.f;
#pragma unroll
        for (int j = 0; j < 31; j++) {
            const float p = s[j];
            float vv[16];
#pragma unroll
            for (int d4 = 0; d4 < 16; d4 += 4)
                *(float4*)&vv[d4] = *(const float4*)&vs[tid + j][c*16 + d4];
#pragma unroll
            for (int d = 0; d < 16; d++)
                o[d] = fmaf(p, vv[d], o[d]);
        }
#pragma unroll
        for (int d = 0; d < 16; d += 2)
            *(__half2*)&op[c*16 + d] = __halves2half2(__float2half_rn(o[d]*inv),
                                                      __float2half_rn(o[d+1]*inv));
    }
}

// ---------------- LayerNorm (+clip), dual output ----------------------------
template<bool CLIP, bool WF, bool WH>
__global__ __launch_bounds__(128) void ln_kernel(
    const float* __restrict__ a,
    const float* __restrict__ gam, const float* __restrict__ bet,
    float* __restrict__ outf, int ldf,
    __half* __restrict__ outh, int ldh)
{
    const int row = blockIdx.x;
    const int tid = threadIdx.x;
    const float* ap = a + (size_t)row*512;

    float v[4];
    float s = 0.f, s2 = 0.f;
#pragma unroll
    for (int i = 0; i < 4; i++) {
        const float x = ap[tid + 128*i];
        v[i] = x; s += x; s2 += x*x;
    }
    __shared__ float red[2][4];
#pragma unroll
    for (int o = 16; o > 0; o >>= 1) {
        s  += __shfl_down_sync(~0u, s,  o);
        s2 += __shfl_down_sync(~0u, s2, o);
    }
    const int wd = tid >> 5, lane = tid & 31;
    if (lane == 0) { red[0][wd] = s; red[1][wd] = s2; }
    __syncthreads();
    __shared__ float stats[2];
    if (tid == 0) {
        float ts = 0.f, ts2 = 0.f;
#pragma unroll
        for (int w = 0; w < 4; w++) { ts += red[0][w]; ts2 += red[1][w]; }
        const float mean = ts * (1.f/512.f);
        stats[0] = mean;
        stats[1] = rsqrtf(ts2 * (1.f/512.f) - mean*mean + 1e-5f);
    }
    __syncthreads();
    const float mean = stats[0], rstd = stats[1];
#pragma unroll
    for (int i = 0; i < 4; i++) {
        const int c = tid + 128*i;
        float y = (v[i] - mean) * rstd * gam[c] + bet[c];
        if (CLIP) y = fminf(fmaxf(y, -100.f), 100.f);
        if (WF) outf[(size_t)row*ldf + c] = y;
        if (WH) outh[(size_t)row*ldh + c] = __float2half_rn(y);
    }
}

// ---------------- partial mean over sequence axis --------------------------
__global__ void mean1_kernel(const float* __restrict__ x, float* __restrict__ outp)
{
    const int c = blockIdx.x*128 + threadIdx.x;
    const int b = blockIdx.y;
    const int z = blockIdx.z;
    const float* p = x + ((size_t)b*LL + z*64)*512 + c;
    float s = 0.f;
#pragma unroll 4
    for (int l = 0; l < 64; l++) s += p[(size_t)l*512];
    outp[(z*BB + b)*512 + c] = s;
}

// ---------------- fused summary: mean2 + @Wg + @Wc[512:] -------------------
__global__ __launch_bounds__(512) void summary_kernel(
    const float* __restrict__ part,
    const float* __restrict__ Wg, const float* __restrict__ bg,
    const float* __restrict__ Wc2, const float* __restrict__ bc,
    float* __restrict__ gpart)
{
    __shared__ float a[512], g[512];
    const int b = blockIdx.x, n = threadIdx.x;
    float s = 0.f;
#pragma unroll
    for (int z = 0; z < 16; z++) s += part[(z*BB + b)*512 + n];
    a[n] = s * (1.f/LL);
    __syncthreads();
    float acc = bg[n];
    for (int k = 0; k < 512; k++) acc = fmaf(a[k], Wg[(size_t)k*512 + n], acc);
    g[n] = acc;
    __syncthreads();
    float acc2 = bc[n];
    for (int k = 0; k < 512; k++) acc2 = fmaf(g[k], Wc2[(size_t)k*512 + n], acc2);
    gpart[b*512 + n] = acc2;
}

// ---------------- bias concat -----------------------------------------------
__global__ void concat_bias_kernel(const float* __restrict__ b1,
                                   const float* __restrict__ b2,
                                   float* __restrict__ o)
{
    const int i = threadIdx.x;
    o[i] = (i < 256) ? b1[i] : b2[i - 256];
}

// ---------------- small-N GEMM (N=5), K=256 --------------------------------
__global__ void small_gemm_kernel(
    const float* __restrict__ A, int lda, const float* __restrict__ W,
    const float* __restrict__ bias, float* __restrict__ C, int N)
{
    const int idx = blockIdx.x*blockDim.x + threadIdx.x;
    if (idx >= MROWS*N) return;
    const int m = idx / N, n = idx - m*N;
    const float* a = A + (size_t)m*lda;
    float s0 = bias[n], s1 = 0.f, s2 = 0.f, s3 = 0.f;
    for (int k = 0; k < 256; k += 4) {
        const float4 av = *(const float4*)&a[k];
        s0 = fmaf(av.x, W[(k  )*N + n], s0);
        s1 = fmaf(av.y, W[(k+1)*N + n], s1);
        s2 = fmaf(av.z, W[(k+2)*N + n], s2);
        s3 = fmaf(av.w, W[(k+3)*N + n], s3);
    }
    C[idx] = (s0 + s1) + (s2 + s3);
}

// ---------------- fused type head: logits + softmax@emb --------------------
__global__ __launch_bounds__(256) void type_head_kernel(
    const float* __restrict__ h,
    const float* __restrict__ Wt2, const float* __restrict__ bt2,
    const float* __restrict__ emb,
    float* __restrict__ out_logits,
    __half* __restrict__ si)
{
    __shared__ float As[8][260];
    __shared__ float lg[8][18];
    const int tid = threadIdx.x;
    const int r0 = blockIdx.x * 8;

#pragma unroll
    for (int it = 0; it < 2; it++) {
        const int idx = tid + it*256;
        const int r = idx >> 6;
        const int c4 = (idx & 63) * 4;
        *(float4*)&As[r][c4] = *(const float4*)&h[((size_t)(r0 + r))*256 + c4];
    }
    __syncthreads();

    if (tid < 144) {
        const int r = tid / 18, n = tid - r*18;
        float s0 = bt2[n], s1 = 0.f, s2 = 0.f, s3 = 0.f;
        for (int k = 0; k < 256; k += 4) {
            const float4 av = *(const float4*)&As[r][k];
            s0 = fmaf(av.x, Wt2[(k  )*18 + n], s0);
            s1 = fmaf(av.y, Wt2[(k+1)*18 + n], s1);
            s2 = fmaf(av.z, Wt2[(k+2)*18 + n], s2);
            s3 = fmaf(av.w, Wt2[(k+3)*18 + n], s3);
        }
        const float v = (s0 + s1) + (s2 + s3);
        lg[r][n] = v;
        out_logits[(size_t)(r0 + r)*18 + n] = v;
    }
    __syncthreads();

    const int w = tid >> 5, lane = tid & 31;
    float v[18];
    float mx = -1e30f;
#pragma unroll
    for (int j = 0; j < 18; j++) { v[j] = lg[w][j]; mx = fmaxf(mx, v[j]); }
    float sum = 0.f;
#pragma unroll
    for (int j = 0; j < 18; j++) { v[j] = expf(v[j] - mx); sum += v[j]; }
    const float inv = 1.f / sum;
    float o = 0.f;
#pragma unroll
    for (int j = 0; j < 18; j++) o = fmaf(v[j], emb[j*32 + lane], o);
    si[(size_t)(r0 + w)*544 + 512 + lane] = __float2half_rn(o * inv);
}

// ---------------- launch ----------------------------------------------------
extern "C" void kernel_launch(void* const* d_in, const int* in_sizes, int n_in,
                              void* d_out, int out_size)
{
    (void)in_sizes; (void)n_in; (void)out_size;
    const float* state = (const float*)d_in[0];
    const float* Wp    = (const float*)d_in[1];
    const float* bp    = (const float*)d_in[2];
    const float* Wqkv  = (const float*)d_in[3];
    const float* bqkv  = (const float*)d_in[4];
    const float* Wo    = (const float*)d_in[5];
    const float* bo    = (const float*)d_in[6];
    const float* ln_g  = (const float*)d_in[7];
    const float* ln_b  = (const float*)d_in[8];
    const float* Wg    = (const float*)d_in[9];
    const float* bg    = (const float*)d_in[10];
    const float* Wc    = (const float*)d_in[11];
    const float* bc    = (const float*)d_in[12];
    const float* W1    = (const float*)d_in[13];
    const float* b1    = (const float*)d_in[14];
    const float* W2    = (const float*)d_in[15];
    const float* b2    = (const float*)d_in[16];
    const float* fn_g  = (const float*)d_in[17];
    const float* fn_b  = (const float*)d_in[18];
    const float* Wt1   = (const float*)d_in[19];
    const float* bt1   = (const float*)d_in[20];
    const float* Wt2   = (const float*)d_in[21];
    const float* bt2   = (const float*)d_in[22];
    const float* temb  = (const float*)d_in[23];
    const float* Ws1   = (const float*)d_in[24];
    const float* bs1   = (const float*)d_in[25];
    const float* Ws2   = (const float*)d_in[26];
    const float* bs2   = (const float*)d_in[27];
    const float* Wa1   = (const float*)d_in[28];
    const float* ba1   = (const float*)d_in[29];
    const float* Wa2   = (const float*)d_in[30];
    const float* ba2   = (const float*)d_in[31];

    float* out = (float*)d_out;

    static float *px=nullptr,*ploc,*pqkv,*pattf,*ptmp,*pcomb,*ph256,*ppm,*pgpart,*pbsa;
    static __half *pxh,*ploch,*patth,*ptmp1h,*pcombh,*psih,*psteh,*pwt;
    if (!px) {
        cudaGetSymbolAddress((void**)&px,    g_x);
        cudaGetSymbolAddress((void**)&pxh,   g_xh);
        cudaGetSymbolAddress((void**)&ploc,  g_loc);
        cudaGetSymbolAddress((void**)&ploch, g_loch);
        cudaGetSymbolAddress((void**)&pqkv,  g_qkv);
        cudaGetSymbolAddress((void**)&pattf, g_att);
        cudaGetSymbolAddress((void**)&patth, g_atth);
        cudaGetSymbolAddress((void**)&ptmp,  g_tmp);
        cudaGetSymbolAddress((void**)&ptmp1h,g_tmp1h);
        cudaGetSymbolAddress((void**)&pcomb, g_comb);
        cudaGetSymbolAddress((void**)&pcombh,g_combh);
        cudaGetSymbolAddress((void**)&psih,  g_sih);
        cudaGetSymbolAddress((void**)&ph256, g_h256);
        cudaGetSymbolAddress((void**)&ppm,   g_pmean);
        cudaGetSymbolAddress((void**)&pgpart,g_gpart);
        cudaGetSymbolAddress((void**)&pbsa,  g_bsa);
        cudaGetSymbolAddress((void**)&psteh, g_steh);
        cudaGetSymbolAddress((void**)&pwt,   g_wt);
        cudaFuncSetAttribute(gemm_h<0,false,false,true ,true >, cudaFuncAttributeMaxDynamicSharedMemorySize, SMEM_H);
        cudaFuncSetAttribute(gemm_h<0,false,false,true ,false>, cudaFuncAttributeMaxDynamicSharedMemorySize, SMEM_H);
        cudaFuncSetAttribute(gemm_h<0,false,true ,true ,false>, cudaFuncAttributeMaxDynamicSharedMemorySize, SMEM_H);
        cudaFuncSetAttribute(gemm_h<0,true ,false,true ,true >, cudaFuncAttributeMaxDynamicSharedMemorySize, SMEM_H);
        cudaFuncSetAttribute(gemm_h<2,false,false,false,true >, cudaFuncAttributeMaxDynamicSharedMemorySize, SMEM_H);
        cudaFuncSetAttribute(gemm_h<1,false,false,true ,false>, cudaFuncAttributeMaxDynamicSharedMemorySize, SMEM_H);
        cudaFuncSetAttribute(natten_kernel, cudaFuncAttributeMaxDynamicSharedMemorySize, SMEM_NAT);
    }

    // 0. transposed fp16 weights + fp16 state + concat bias
    {
        TransJobs J;
        const float* srcs[NJOBS] = { Wp, Wqkv, Wqkv + (size_t)512*1536, Wo,
                                     Wo + (size_t)512*512, Wc, W1, W2, Wt1, Ws1, Wa1 };
        const long long offs[NJOBS] = { WT_P, WT_QKV0, WT_QKV1, WT_O0, WT_O1,
                                        WT_C, WT_1, WT_2, WT_T1, WT_SA, WT_SA + 256*544 };
        const int Ks[NJOBS] = { 256, 512, 512, 512, 512, 512, 512, 1024, 512, 544, 544 };
        const int Ns[NJOBS] = { 512, 1536, 1536, 512, 512, 512, 1024, 512, 256, 256, 256 };
        int acc = 0;
        for (int i = 0; i < NJOBS; i++) {
            J.src[i] = srcs[i]; J.dstoff[i] = offs[i]; J.K[i] = Ks[i]; J.N[i] = Ns[i];
            J.start[i] = acc;
            acc += (Ns[i] >> 5) * (Ks[i] >> 5);
        }
        J.start[NJOBS] = acc;
        transpose_all_kernel<<<acc, 256>>>(J, pwt);
    }
    tohalf_kernel<<<(MROWS*DIN/2 + 255)/256, 256>>>(state, psteh, MROWS*DIN/2);
    concat_bias_kernel<<<1, 512>>>(bs1, ba1, pbsa);

    const dim3 thr(256);
    #define GEMM(T1,T2,T3,T4,T5, Ap, LDA, WT, BIAS, GB, RESP, CF, CH, NN, KK) \
        gemm_h<T1,T2,T3,T4,T5><<<dim3((NN)/128, MROWS/128), thr, SMEM_H>>>(Ap, LDA, WT, BIAS, GB, RESP, CF, CH, NN, KK)

    // 1. x = state @ Wp + bp  (f32 + fp16)
    GEMM(0,false,false,true,true, psteh, DIN, pwt+WT_P, bp, nullptr, nullptr, px, pxh, 512, 256);

    // 2. two NATTEN layers
    const float*  locF = px;
    const __half* locH = pxh;
    for (int i = 0; i < 2; i++) {
        GEMM(0,false,false,true,false, locH, 512, pwt + (i ? WT_QKV1 : WT_QKV0), bqkv + i*1536,
             nullptr, nullptr, pqkv, (__half*)nullptr, 1536, 512);
        natten_kernel<<<dim3(LL/64, NHEAD, BB), 64, SMEM_NAT>>>(pqkv, patth);
        GEMM(0,false,true,true,false, patth, 512, pwt + (i ? WT_O1 : WT_O0), bo + i*512,
             nullptr, locF, ptmp, (__half*)nullptr, 512, 512);
        ln_kernel<false,true,true><<<MROWS, 128>>>(ptmp, ln_g + i*512, ln_b + i*512,
                                                   ploc, 512, ploch, 512);
        locF = ploc; locH = ploch;
    }

    // 3. global summary path (per-batch, f32 exact)
    mean1_kernel<<<dim3(4, BB, 16), 128>>>(px, ppm);
    summary_kernel<<<BB, 512>>>(ppm, Wg, bg, Wc + (size_t)512*512, bc, pgpart);

    // 4. comb = loc @ Wc[:512] + gpart[batch]  (f32 + fp16)
    GEMM(0,true,false,true,true, ploch, 512, pwt+WT_C, nullptr, pgpart, nullptr,
         pcomb, pcombh, 512, 512);

    // 5. FFN (hidden fp16 only; residual fused into W2) + LN(clip) -> si_h
    GEMM(2,false,false,false,true, pcombh, 512, pwt+WT_1, b1, nullptr, nullptr,
         (float*)nullptr, ptmp1h, 1024, 512);
    GEMM(0,false,true,true,false, ptmp1h, 1024, pwt+WT_2, b2, nullptr, pcomb,
         pattf, (__half*)nullptr, 512, 1024);
    ln_kernel<true,false,true><<<MROWS, 128>>>(pattf, fn_g, fn_b,
                                               (float*)nullptr, 0, psih, 544);

    // 6. type head
    GEMM(1,false,false,true,false, psih, 544, pwt+WT_T1, bt1, nullptr, nullptr,
         ph256, (__half*)nullptr, 256, 512);
    type_head_kernel<<<MROWS/8, 256>>>(ph256, Wt2, bt2, temb, out, psih);

    // 7+8. fused size+amount first layer
    GEMM(1,false,false,true,false, psih, 544, pwt+WT_SA, pbsa, nullptr, nullptr,
         ptmp, (__half*)nullptr, 512, 544);
    small_gemm_kernel<<<(MROWS*5 + 255)/256, 256>>>(ptmp,       512, Ws2, bs2, out + (size_t)MROWS*18, 5);
    small_gemm_kernel<<<(MROWS*5 + 255)/256, 256>>>(ptmp + 256, 512, Wa2, ba2, out + (size_t)MROWS*23, 5);
}